// round 8
// baseline (speedup 1.0000x reference)
#include <cuda_runtime.h>

// DiarizationLoss: B=32, T=65536, S=4, scalar output.
// Single fused kernel, dynamic tile scheduler over ACTIVE elements only.

#define NB 32
#define NT 65536
#define CEPS 1e-7f
#define LN2F 0.69314718055994531f

#define THREADS 512
#define TILE 1024                   // elements per tile = THREADS * 2
#define GRID 304                    // 2 blocks/SM x 152 SMs

__device__ float g_part[NB][21];
__device__ unsigned int g_count;
__device__ unsigned int g_ticket;

// lengths dtype probe: values in [32768,65536), nonzero.
// int64 LE => word1 (hi of lengths[0]) == 0 ; int32 => word1 >= 32768.
__device__ __forceinline__ int load_len(const int* __restrict__ p32, int b) {
    return (p32[1] == 0) ? p32[2 * b] : p32[b];
}

__global__ __launch_bounds__(THREADS, 2) void diar_loss_kernel(
    const float* __restrict__ ps,
    const float* __restrict__ pv,
    const float* __restrict__ lb,
    const float* __restrict__ vad,
    const int*   __restrict__ len32,
    float*       __restrict__ out)
{
    const int tid = threadIdx.x;

    __shared__ int s_len[NB];
    __shared__ int s_prefix[NB + 1];
    __shared__ int s_tk[2];
    __shared__ float sm[21][16];

    if (tid < 32) {
        int l = load_len(len32, tid);
        s_len[tid] = l;
        int x = (l + TILE - 1) >> 10;          // tiles for this batch
        #pragma unroll
        for (int o = 1; o < 32; o <<= 1) {     // inclusive warp scan
            int y = __shfl_up_sync(0xffffffffu, x, o);
            if (tid >= o) x += y;
        }
        s_prefix[tid + 1] = x;
        if (tid == 0) { s_prefix[0] = 0; s_tk[0] = (int)atomicAdd(&g_ticket, 1u); }
    }
    __syncthreads();
    const int total = s_prefix[NB];

    float acc[21];
    #pragma unroll
    for (int k = 0; k < 21; k++) acc[k] = 0.0f;
    int cur_b = -1;

    const int lane = tid & 31;
    const int w    = tid >> 5;

    auto flush = [&](int bb) {
        #pragma unroll
        for (int k = 0; k < 21; k++) {
            float v = acc[k];
            v += __shfl_down_sync(0xffffffffu, v, 16);
            v += __shfl_down_sync(0xffffffffu, v, 8);
            v += __shfl_down_sync(0xffffffffu, v, 4);
            v += __shfl_down_sync(0xffffffffu, v, 2);
            v += __shfl_down_sync(0xffffffffu, v, 1);
            if (lane == 0) sm[k][w] = v;
            acc[k] = 0.0f;
        }
        __syncthreads();
        if (tid < 21) {
            float v = 0.0f;
            #pragma unroll
            for (int ww = 0; ww < 16; ww++) v += sm[tid][ww];
            atomicAdd(&g_part[bb][tid], v);
        }
        __syncthreads();
    };

    int buf = 0;
    int tk = s_tk[0];
    while (tk < total) {
        if (tid == 0) s_tk[buf ^ 1] = (int)atomicAdd(&g_ticket, 1u);  // prefetch

        // batch lookup
        int b = 0;
        #pragma unroll
        for (int i = 1; i < NB; i++) b += (tk >= s_prefix[i]);
        if (b != cur_b) { if (cur_b >= 0) flush(cur_b); cur_b = b; }

        const int len = s_len[b];
        const int t   = ((tk - s_prefix[b]) << 10) + 2 * tid;

        const float4* __restrict__ psb  = (const float4*)(ps + (size_t)b * NT * 4);
        const float4* __restrict__ lbb  = (const float4*)(lb + (size_t)b * NT * 4);
        const float2* __restrict__ pv2b = (const float2*)(pv  + (size_t)b * NT);
        const float2* __restrict__ v2b  = (const float2*)(vad + (size_t)b * NT);

        float4 P0 = psb[t], P1 = psb[t + 1];
        float4 L0 = lbb[t], L1 = lbb[t + 1];
        float2 pv2 = pv2b[t >> 1];
        float2 v2  = v2b[t >> 1];
        const float m0 = (t     < len) ? 1.0f : 0.0f;
        const float m1 = (t + 1 < len) ? 1.0f : 0.0f;

        // base-2 logs; ln2 folded into finalize. m applies length mask.
        #pragma unroll
        for (int e = 0; e < 2; e++) {
            float4 p4 = e ? P1 : P0;
            float4 l4 = e ? L1 : L0;
            float m   = e ? m1 : m0;
            float pvv = e ? pv2.y : pv2.x;
            float v   = e ? v2.y  : v2.x;
            float pp[4] = {p4.x, p4.y, p4.z, p4.w};
            float ll[4] = {l4.x * m, l4.y * m, l4.z * m, l4.w * m};
            float d[4];
            #pragma unroll
            for (int i = 0; i < 4; i++) {
                float p  = fminf(fmaxf(pp[i], CEPS), 1.0f - CEPS);
                float lq = __log2f(1.0f - p);
                float lp = __log2f(p);
                d[i] = lp - lq;
                acc[16 + i] += lq * m;
            }
            #pragma unroll
            for (int i = 0; i < 4; i++)
                #pragma unroll
                for (int j = 0; j < 4; j++)
                    acc[i * 4 + j] += d[i] * ll[j];
            pvv = fminf(fmaxf(pvv, CEPS), 1.0f - CEPS);
            float arg = (v > 0.5f) ? pvv : (1.0f - pvv);
            acc[20] -= __log2f(arg) * m;
        }

        __syncthreads();            // prefetch ticket visible to all
        tk = s_tk[buf ^ 1];
        buf ^= 1;
    }
    if (cur_b >= 0) flush(cur_b);

    // ---- last-block finalize ----
    __shared__ int s_last;
    if (tid == 0) {
        __threadfence();
        unsigned prev = atomicAdd(&g_count, 1u);
        s_last = (prev == (unsigned)(GRID - 1));
    }
    __syncthreads();
    if (!s_last) return;
    __threadfence();

    if (tid < NB) {
        const int bb = tid;
        const float msum = (float)s_len[bb];
        const float scal = LN2F / msum;

        float L[4][4];
        #pragma unroll
        for (int i = 0; i < 4; i++)
            #pragma unroll
            for (int j = 0; j < 4; j++)
                L[i][j] = -(g_part[bb][i * 4 + j] + g_part[bb][16 + i]) * scal;

        float best = 3.4e38f;
        #pragma unroll
        for (int a = 0; a < 4; a++)
            #pragma unroll
            for (int cc = 0; cc < 4; cc++) {
                if (cc == a) continue;
                #pragma unroll
                for (int e = 0; e < 4; e++) {
                    if (e == a || e == cc) continue;
                    int f = 6 - a - cc - e;
                    best = fminf(best, L[0][a] + L[1][cc] + L[2][e] + L[3][f]);
                }
            }
        best *= 0.25f;

        float sb = best, sv = g_part[bb][20] * LN2F, sd = msum;
        #pragma unroll
        for (int off = 16; off >= 1; off >>= 1) {
            sb += __shfl_xor_sync(0xffffffffu, sb, off);
            sv += __shfl_xor_sync(0xffffffffu, sv, off);
            sd += __shfl_xor_sync(0xffffffffu, sd, off);
        }
        if (bb == 0)
            out[0] = (sb / (float)NB) + 0.5f * (sv / sd);
    }
    __syncthreads();

    // reset scratch for next graph replay
    for (int i = tid; i < NB * 21; i += THREADS)
        ((float*)g_part)[i] = 0.0f;
    if (tid == 0) { g_count = 0u; g_ticket = 0u; }
}

extern "C" void kernel_launch(void* const* d_in, const int* in_sizes, int n_in,
                              void* d_out, int out_size)
{
    diar_loss_kernel<<<GRID, THREADS>>>(
        (const float*)d_in[0], (const float*)d_in[1],
        (const float*)d_in[2], (const float*)d_in[3],
        (const int*)d_in[4], (float*)d_out);
}

// round 9
// speedup vs baseline: 1.5427x; 1.5427x over previous
#include <cuda_runtime.h>

// DiarizationLoss: B=32, T=65536, S=4, scalar output. Single fused kernel.
// R6 structure (ILP-4 groups) + uniform masked path (no scalar boundary loop).

#define NB 32
#define NT 65536
#define CEPS 1e-7f
#define LN2F 0.69314718055994531f

#define CHUNKS 16
#define THREADS 256
#define CHUNK_T (NT / CHUNKS)              // 4096
#define GROUPS (CHUNK_T / (THREADS * 4))   // 4 groups of 4 elements per thread
#define GRID (NB * CHUNKS)                 // 512 blocks

__device__ float g_part[NB][21];
__device__ unsigned int g_count;

// lengths dtype probe: values in [32768,65536), nonzero.
// int64 LE => word1 (hi of lengths[0]) == 0 ; int32 => word1 >= 32768.
__device__ __forceinline__ int load_len(const int* __restrict__ p32, int b) {
    return (p32[1] == 0) ? p32[2 * b] : p32[b];
}

__global__ __launch_bounds__(THREADS, 3) void diar_loss_kernel(
    const float* __restrict__ ps,
    const float* __restrict__ pv,
    const float* __restrict__ lb,
    const float* __restrict__ vad,
    const int*   __restrict__ len32,
    float*       __restrict__ out)
{
    const int b     = blockIdx.x >> 4;           // / CHUNKS
    const int chunk = blockIdx.x & (CHUNKS - 1);
    const int len   = load_len(len32, b);
    const int t0    = chunk * CHUNK_T;

    if (t0 < len) {
        float acc[21];
        #pragma unroll
        for (int k = 0; k < 21; k++) acc[k] = 0.0f;

        const float4* __restrict__ psb  = (const float4*)(ps + (size_t)b * NT * 4);
        const float4* __restrict__ lbb  = (const float4*)(lb + (size_t)b * NT * 4);
        const float4* __restrict__ pv4b = (const float4*)(pv  + (size_t)b * NT);
        const float4* __restrict__ v4b  = (const float4*)(vad + (size_t)b * NT);

        // base-2 logs; ln2 folded into finalize. m in {0,1} applies length mask.
        auto elem = [&](float4 p4, float4 l4, float pvv, float v, float m) {
            float pp[4] = {p4.x, p4.y, p4.z, p4.w};
            float ll[4] = {l4.x * m, l4.y * m, l4.z * m, l4.w * m};
            float d[4];
            #pragma unroll
            for (int i = 0; i < 4; i++) {
                float p  = fminf(fmaxf(pp[i], CEPS), 1.0f - CEPS);
                float lq = __log2f(1.0f - p);
                float lp = __log2f(p);
                d[i] = lp - lq;
                acc[16 + i] += lq * m;
            }
            #pragma unroll
            for (int i = 0; i < 4; i++)
                #pragma unroll
                for (int j = 0; j < 4; j++)
                    acc[i * 4 + j] += d[i] * ll[j];
            pvv = fminf(fmaxf(pvv, CEPS), 1.0f - CEPS);
            float arg = (v > 0.5f) ? pvv : (1.0f - pvv);
            acc[20] -= __log2f(arg) * m;
        };

        // uniform ILP-4 path for ALL non-skipped chunks (mask handles the tail)
        #pragma unroll
        for (int g = 0; g < GROUPS; g++) {
            const int tg = t0 + 4 * threadIdx.x + g * (THREADS * 4);
            float4 P0 = psb[tg],     P1 = psb[tg + 1];
            float4 P2 = psb[tg + 2], P3 = psb[tg + 3];
            float4 L0 = lbb[tg],     L1 = lbb[tg + 1];
            float4 L2 = lbb[tg + 2], L3 = lbb[tg + 3];
            float4 pv4 = pv4b[tg >> 2];
            float4 v4  = v4b[tg >> 2];
            float m0 = (tg     < len) ? 1.0f : 0.0f;
            float m1 = (tg + 1 < len) ? 1.0f : 0.0f;
            float m2 = (tg + 2 < len) ? 1.0f : 0.0f;
            float m3 = (tg + 3 < len) ? 1.0f : 0.0f;
            elem(P0, L0, pv4.x, v4.x, m0);
            elem(P1, L1, pv4.y, v4.y, m1);
            elem(P2, L2, pv4.z, v4.z, m2);
            elem(P3, L3, pv4.w, v4.w, m3);
        }

        // block reduction: warp shuffle -> shared -> one RED per value
        __shared__ float sm[21][8];
        const int lane = threadIdx.x & 31;
        const int w    = threadIdx.x >> 5;
        #pragma unroll
        for (int k = 0; k < 21; k++) {
            float v = acc[k];
            v += __shfl_down_sync(0xffffffffu, v, 16);
            v += __shfl_down_sync(0xffffffffu, v, 8);
            v += __shfl_down_sync(0xffffffffu, v, 4);
            v += __shfl_down_sync(0xffffffffu, v, 2);
            v += __shfl_down_sync(0xffffffffu, v, 1);
            if (lane == 0) sm[k][w] = v;
        }
        __syncthreads();
        if (threadIdx.x < 21) {
            float v = 0.0f;
            #pragma unroll
            for (int ww = 0; ww < 8; ww++) v += sm[threadIdx.x][ww];
            atomicAdd(&g_part[b][threadIdx.x], v);
        }
    }

    // ---- last-block finalize ----
    __shared__ int s_last;
    if (threadIdx.x == 0) {
        __threadfence();
        unsigned prev = atomicAdd(&g_count, 1u);
        s_last = (prev == (unsigned)(GRID - 1));
    }
    __syncthreads();
    if (!s_last) return;
    __threadfence();

    if (threadIdx.x < NB) {
        const int bb = threadIdx.x;
        const float msum = (float)load_len(len32, bb);
        const float scal = LN2F / msum;   // fold ln2 (base-2 logs) here

        float L[4][4];
        #pragma unroll
        for (int i = 0; i < 4; i++)
            #pragma unroll
            for (int j = 0; j < 4; j++)
                L[i][j] = -(g_part[bb][i * 4 + j] + g_part[bb][16 + i]) * scal;

        float best = 3.4e38f;
        #pragma unroll
        for (int a = 0; a < 4; a++)
            #pragma unroll
            for (int cc = 0; cc < 4; cc++) {
                if (cc == a) continue;
                #pragma unroll
                for (int e = 0; e < 4; e++) {
                    if (e == a || e == cc) continue;
                    int f = 6 - a - cc - e;
                    best = fminf(best, L[0][a] + L[1][cc] + L[2][e] + L[3][f]);
                }
            }
        best *= 0.25f;

        float sb = best, sv = g_part[bb][20] * LN2F, sd = msum;
        #pragma unroll
        for (int off = 16; off >= 1; off >>= 1) {
            sb += __shfl_xor_sync(0xffffffffu, sb, off);
            sv += __shfl_xor_sync(0xffffffffu, sv, off);
            sd += __shfl_xor_sync(0xffffffffu, sd, off);
        }
        if (bb == 0)
            out[0] = (sb / (float)NB) + 0.5f * (sv / sd);
    }
    __syncthreads();

    // reset scratch for next graph replay
    for (int i = threadIdx.x; i < NB * 21; i += THREADS)
        ((float*)g_part)[i] = 0.0f;
    if (threadIdx.x == 0) g_count = 0u;
}

extern "C" void kernel_launch(void* const* d_in, const int* in_sizes, int n_in,
                              void* d_out, int out_size)
{
    diar_loss_kernel<<<GRID, THREADS>>>(
        (const float*)d_in[0], (const float*)d_in[1],
        (const float*)d_in[2], (const float*)d_in[3],
        (const int*)d_in[4], (float*)d_out);
}